// round 12
// baseline (speedup 1.0000x reference)
#include <cuda_runtime.h>
#include <cuda_bf16.h>
#include <cstdint>

// FlowBasedDensityPotential: energy = 0.5 * sum(|grad phi|^2), central diffs
// (one-sided at boundaries) on 2048x2048 f32. 'pos' input is dead.
//
// R12: hybrid of the two best-measured runs (R4/R10, both 9.57us in-kernel,
// both async-copy + staged consumption). Grid 512 (4 CTAs/SM) x 4 rows;
// each CTA issues TWO independent bulk copies at t=0 (4-row + 2-row chunks,
// separate mbarriers) and computes rows 0-1 as soon as chunk A lands.
// Maximizes TMA queue depth (8 copies/SM in flight) while keeping staged
// waits. If this is still ~10.5us the plateau is a hard chip-level floor.

#define NX 2048
#define NY 2048
#define BLOCK 256
#define ROWS_PER_CTA 4
#define NUM_BLOCKS (NX / ROWS_PER_CTA)     // 512
#define PITCH NY
#define ROW_BYTES (NY * 4)                  // 8192
#define SROWS 6                             // 4 computed + 2 halo
#define TILE_BYTES (SROWS * ROW_BYTES)      // 49152
#define FINAL_SCALE 524288.0                // 0.5 * (1/(2h))^2

__device__ double       g_partials[NUM_BLOCKS];
__device__ unsigned int g_ticket = 0;

extern __shared__ float s_tile[];           // SROWS * PITCH floats

__device__ __forceinline__ void mbar_init(unsigned int mbar, unsigned int cnt) {
    asm volatile("mbarrier.init.shared.b64 [%0], %1;" :: "r"(mbar), "r"(cnt) : "memory");
}
__device__ __forceinline__ void mbar_expect_tx(unsigned int mbar, unsigned int bytes) {
    asm volatile("mbarrier.arrive.expect_tx.shared.b64 _, [%0], %1;"
                 :: "r"(mbar), "r"(bytes) : "memory");
}
__device__ __forceinline__ void bulk_g2s(unsigned int sdst, const void* gsrc,
                                         unsigned int bytes, unsigned int mbar) {
    asm volatile("cp.async.bulk.shared::cta.global.mbarrier::complete_tx::bytes "
                 "[%0], [%1], %2, [%3];"
                 :: "r"(sdst), "l"(gsrc), "r"(bytes), "r"(mbar) : "memory");
}
__device__ __forceinline__ void mbar_wait(unsigned int mbar, unsigned int phase) {
    asm volatile("{\n\t"
                 ".reg .pred p;\n\t"
                 "WL%=:\n\t"
                 "mbarrier.try_wait.parity.shared.b64 p, [%0], %1;\n\t"
                 "@!p bra WL%=;\n\t"
                 "}" :: "r"(mbar), "r"(phase) : "memory");
}

__global__ void __launch_bounds__(BLOCK, 4)
flow_energy_kernel(const float* __restrict__ phi, float* __restrict__ out)
{
    __shared__ __align__(8) unsigned long long s_bar[2];
    __shared__ float  s_warp[BLOCK / 32];
    __shared__ double s_dwarp[BLOCK / 32];
    __shared__ bool   s_is_last;

    const int tid = threadIdx.x;
    const int b   = blockIdx.x;
    const int r0  = b * ROWS_PER_CTA;

    const unsigned int sbase = (unsigned int)__cvta_generic_to_shared(s_tile);
    const unsigned int bar0  = (unsigned int)__cvta_generic_to_shared(&s_bar[0]);
    const unsigned int bar1  = (unsigned int)__cvta_generic_to_shared(&s_bar[1]);

    if (tid == 0) {
        mbar_init(bar0, 1);
        mbar_init(bar1, 1);
    }
    __syncthreads();

    if (tid == 0) {
        // Chunk A: smem slots (b==0 ? 1 : 0)..3  == rows max(r0-1,0)..r0+2.
        const int gsA   = (b == 0) ? 0 : r0 - 1;
        const int slotA = (b == 0) ? 1 : 0;
        const unsigned int bytesA = (unsigned int)((4 - slotA) * ROW_BYTES);
        mbar_expect_tx(bar0, bytesA);
        bulk_g2s(sbase + (unsigned int)(slotA * ROW_BYTES),
                 phi + (size_t)gsA * NY, bytesA, bar0);

        // Chunk B: smem slots 4..(last? 4 : 5) == rows r0+3..min(r0+4, NX-1).
        const int geB = (b == NUM_BLOCKS - 1) ? NX - 1 : r0 + 4;
        const unsigned int bytesB = (unsigned int)((geB - (r0 + 3) + 1) * ROW_BYTES);
        mbar_expect_tx(bar1, bytesB);
        bulk_g2s(sbase + (unsigned int)(4 * ROW_BYTES),
                 phi + (size_t)(r0 + 3) * NY, bytesB, bar1);
    }

    float acc = 0.0f;

    // Half h computes rows r0+2h, r0+2h+1 (slots 2h+1, 2h+2; window 2h..2h+3).
    #pragma unroll
    for (int h = 0; h < 2; ++h) {
        mbar_wait(h == 0 ? bar0 : bar1, 0);

        #pragma unroll
        for (int pass = 0; pass < 2; ++pass) {
            const int cg = tid + pass * BLOCK;    // 0..511 column chunk
            const int c  = cg * 4;
            const int s0 = h * 2;

            float4 w[4];
            #pragma unroll
            for (int k = 0; k < 4; ++k)
                w[k] = *reinterpret_cast<const float4*>(s_tile + (s0 + k) * PITCH + c);

            #pragma unroll
            for (int r = 0; r < 2; ++r) {
                const int slot = s0 + 1 + r;
                const int gi   = r0 + h * 2 + r;
                const float4 up   = w[r];
                const float4 cur  = w[r + 1];
                const float4 down = w[r + 2];

                float ex, ey, ez, ew;
                if (gi == 0) {
                    ex = (down.x - cur.x) * 2.0f;
                    ey = (down.y - cur.y) * 2.0f;
                    ez = (down.z - cur.z) * 2.0f;
                    ew = (down.w - cur.w) * 2.0f;
                } else if (gi == NX - 1) {
                    ex = (cur.x - up.x) * 2.0f;
                    ey = (cur.y - up.y) * 2.0f;
                    ez = (cur.z - up.z) * 2.0f;
                    ew = (cur.w - up.w) * 2.0f;
                } else {
                    ex = down.x - up.x;
                    ey = down.y - up.y;
                    ez = down.z - up.z;
                    ew = down.w - up.w;
                }

                // y halos from smem; clamped index stays in-bounds (clamped
                // values are select-discarded, never arithmetic inputs).
                const float left  = s_tile[slot * PITCH + c - 1 + (c == 0 ? 1 : 0)];
                const float right = s_tile[slot * PITCH + c + 4 - (c + 4 == NY ? 1 : 0)];

                const float d0 = (c == 0)      ? (cur.y - cur.x) * 2.0f : (cur.y - left);
                const float d1 = cur.z - cur.x;
                const float d2 = cur.w - cur.y;
                const float d3 = (c + 4 == NY) ? (cur.w - cur.z) * 2.0f : (right - cur.z);

                acc += ex * ex + d0 * d0;
                acc += ey * ey + d1 * d1;
                acc += ez * ez + d2 * d2;
                acc += ew * ew + d3 * d3;
            }
        }
    }

    // ---- block reduction ----
    #pragma unroll
    for (int off = 16; off; off >>= 1)
        acc += __shfl_xor_sync(0xffffffffu, acc, off);

    if ((tid & 31) == 0)
        s_warp[tid >> 5] = acc;
    __syncthreads();

    if (tid < 32) {
        float v = (tid < BLOCK / 32) ? s_warp[tid] : 0.0f;
        #pragma unroll
        for (int off = 4; off; off >>= 1)
            v += __shfl_xor_sync(0xffffffffu, v, off);
        if (tid == 0) {
            g_partials[blockIdx.x] = (double)v;
            __threadfence();
            unsigned int tk = atomicAdd(&g_ticket, 1u);
            s_is_last = (tk == (unsigned int)(gridDim.x - 1));
        }
    }
    __syncthreads();

    // ---- last block: sum 512 double partials, scale, write, reset ----
    if (s_is_last) {
        double d = 0.0;
        for (int k = tid; k < NUM_BLOCKS; k += BLOCK)
            d += g_partials[k];
        #pragma unroll
        for (int off = 16; off; off >>= 1)
            d += __shfl_xor_sync(0xffffffffu, d, off);

        if ((tid & 31) == 0)
            s_dwarp[tid >> 5] = d;
        __syncthreads();
        if (tid < 32) {
            double v = (tid < BLOCK / 32) ? s_dwarp[tid] : 0.0;
            #pragma unroll
            for (int off = 4; off; off >>= 1)
                v += __shfl_xor_sync(0xffffffffu, v, off);
            if (tid == 0) {
                out[0] = (float)(v * FINAL_SCALE);
                g_ticket = 0;   // reset for next (graph-replayed) launch
            }
        }
    }
}

extern "C" void kernel_launch(void* const* d_in, const int* in_sizes, int n_in,
                              void* d_out, int out_size)
{
    // Select phi by element count (2048*2048); 'pos' (2,000,000 elems) unused.
    const float* phi = nullptr;
    for (int i = 0; i < n_in; ++i) {
        if (in_sizes[i] == NX * NY) { phi = (const float*)d_in[i]; break; }
    }
    if (!phi) phi = (const float*)d_in[n_in - 1];

    static bool attr_done = false;
    if (!attr_done) {
        cudaFuncSetAttribute(flow_energy_kernel,
                             cudaFuncAttributeMaxDynamicSharedMemorySize,
                             TILE_BYTES);
        attr_done = true;
    }

    flow_energy_kernel<<<NUM_BLOCKS, BLOCK, TILE_BYTES>>>(phi, (float*)d_out);
}

// round 13
// speedup vs baseline: 2.0641x; 2.0641x over previous
#include <cuda_runtime.h>
#include <cuda_bf16.h>
#include <cstdint>

// FlowBasedDensityPotential: energy = 0.5 * sum(|grad phi|^2), central diffs
// (one-sided at boundaries) on 2048x2048 f32. 'pos' input is dead.
//
// R13: maximal-tile TMA. Measured gradient across TMA variants: 80KB tiles
// (R10, 9.57us) > 48KB (R11/R12, 10.2-10.5us) -> bigger copies win. Now:
// 128 CTAs x 16 rows, 144KB smem tile (1 CTA/SM), THREE 6-row bulk copies
// all issued at t=0 on separate mbarriers; compute staged per chunk with
// rolling register windows out of smem.

#define NX 2048
#define NY 2048
#define BLOCK 256
#define ROWS_PER_CTA 16
#define NUM_BLOCKS (NX / ROWS_PER_CTA)     // 128
#define PITCH NY
#define ROW_BYTES (NY * 4)                  // 8192
#define SROWS 18                            // 16 computed + 2 halo
#define TILE_BYTES (SROWS * ROW_BYTES)      // 147456 (144KB)
#define FINAL_SCALE 524288.0                // 0.5 * (1/(2h))^2

__device__ double       g_partials[NUM_BLOCKS];
__device__ unsigned int g_ticket = 0;

extern __shared__ float s_tile[];           // SROWS * PITCH floats

__device__ __forceinline__ void mbar_init(unsigned int mbar, unsigned int cnt) {
    asm volatile("mbarrier.init.shared.b64 [%0], %1;" :: "r"(mbar), "r"(cnt) : "memory");
}
__device__ __forceinline__ void mbar_expect_tx(unsigned int mbar, unsigned int bytes) {
    asm volatile("mbarrier.arrive.expect_tx.shared.b64 _, [%0], %1;"
                 :: "r"(mbar), "r"(bytes) : "memory");
}
__device__ __forceinline__ void bulk_g2s(unsigned int sdst, const void* gsrc,
                                         unsigned int bytes, unsigned int mbar) {
    asm volatile("cp.async.bulk.shared::cta.global.mbarrier::complete_tx::bytes "
                 "[%0], [%1], %2, [%3];"
                 :: "r"(sdst), "l"(gsrc), "r"(bytes), "r"(mbar) : "memory");
}
__device__ __forceinline__ void mbar_wait(unsigned int mbar, unsigned int phase) {
    asm volatile("{\n\t"
                 ".reg .pred p;\n\t"
                 "WL%=:\n\t"
                 "mbarrier.try_wait.parity.shared.b64 p, [%0], %1;\n\t"
                 "@!p bra WL%=;\n\t"
                 "}" :: "r"(mbar), "r"(phase) : "memory");
}

__global__ void __launch_bounds__(BLOCK, 1)
flow_energy_kernel(const float* __restrict__ phi, float* __restrict__ out)
{
    __shared__ __align__(8) unsigned long long s_bar[3];
    __shared__ float  s_warp[BLOCK / 32];
    __shared__ double s_dwarp[BLOCK / 32];
    __shared__ bool   s_is_last;

    const int tid = threadIdx.x;
    const int b   = blockIdx.x;
    const int r0  = b * ROWS_PER_CTA;

    const unsigned int sbase = (unsigned int)__cvta_generic_to_shared(s_tile);
    unsigned int bar[3];
    #pragma unroll
    for (int k = 0; k < 3; ++k)
        bar[k] = (unsigned int)__cvta_generic_to_shared(&s_bar[k]);

    if (tid == 0) {
        mbar_init(bar[0], 1);
        mbar_init(bar[1], 1);
        mbar_init(bar[2], 1);
    }
    __syncthreads();

    if (tid == 0) {
        // Chunk A: smem slots (b==0 ? 1 : 0)..5 == rows max(r0-1,0)..r0+4.
        const int gsA   = (b == 0) ? 0 : r0 - 1;
        const int slotA = (b == 0) ? 1 : 0;
        const unsigned int bytesA = (unsigned int)((6 - slotA) * ROW_BYTES);
        mbar_expect_tx(bar[0], bytesA);
        bulk_g2s(sbase + (unsigned int)(slotA * ROW_BYTES),
                 phi + (size_t)gsA * NY, bytesA, bar[0]);

        // Chunk B: smem slots 6..11 == rows r0+5..r0+10 (always interior).
        const unsigned int bytesB = (unsigned int)(6 * ROW_BYTES);
        mbar_expect_tx(bar[1], bytesB);
        bulk_g2s(sbase + (unsigned int)(6 * ROW_BYTES),
                 phi + (size_t)(r0 + 5) * NY, bytesB, bar[1]);

        // Chunk C: smem slots 12..(last? 16 : 17) == rows r0+11..min(r0+16,NX-1).
        const int geC = (b == NUM_BLOCKS - 1) ? NX - 1 : r0 + 16;
        const unsigned int bytesC = (unsigned int)((geC - (r0 + 11) + 1) * ROW_BYTES);
        mbar_expect_tx(bar[2], bytesC);
        bulk_g2s(sbase + (unsigned int)(12 * ROW_BYTES),
                 phi + (size_t)(r0 + 11) * NY, bytesC, bar[2]);
    }

    float acc = 0.0f;

    // Phase p: window slots s0..s0+nr+1, computed slots s0+1..s0+nr.
    // Phase 0 after A: s0=0, nr=4 (rows r0..r0+3)
    // Phase 1 after B: s0=4, nr=6 (rows r0+4..r0+9)
    // Phase 2 after C: s0=10, nr=6 (rows r0+10..r0+15)
    const int ph_s0[3] = {0, 4, 10};
    const int ph_nr[3] = {4, 6, 6};

    #pragma unroll
    for (int p = 0; p < 3; ++p) {
        mbar_wait(bar[p], 0);
        const int s0 = ph_s0[p];
        const int nr = ph_nr[p];

        #pragma unroll
        for (int pass = 0; pass < 2; ++pass) {
            const int cg = tid + pass * BLOCK;    // 0..511 column chunk
            const int c  = cg * 4;

            float4 w0 = *reinterpret_cast<const float4*>(s_tile + s0 * PITCH + c);
            float4 w1 = *reinterpret_cast<const float4*>(s_tile + (s0 + 1) * PITCH + c);

            #pragma unroll
            for (int r = 0; r < 6; ++r) {
                if (r >= nr) break;
                const int slot = s0 + 1 + r;
                const int gi   = r0 + s0 + r;     // global row of computed slot
                const float4 up   = w0;
                const float4 cur  = w1;
                const float4 down = *reinterpret_cast<const float4*>(
                                        s_tile + (slot + 1) * PITCH + c);

                float ex, ey, ez, ew;
                if (gi == 0) {
                    ex = (down.x - cur.x) * 2.0f;
                    ey = (down.y - cur.y) * 2.0f;
                    ez = (down.z - cur.z) * 2.0f;
                    ew = (down.w - cur.w) * 2.0f;
                } else if (gi == NX - 1) {
                    ex = (cur.x - up.x) * 2.0f;
                    ey = (cur.y - up.y) * 2.0f;
                    ez = (cur.z - up.z) * 2.0f;
                    ew = (cur.w - up.w) * 2.0f;
                } else {
                    ex = down.x - up.x;
                    ey = down.y - up.y;
                    ez = down.z - up.z;
                    ew = down.w - up.w;
                }

                // y halos from smem; clamped index stays in-bounds (clamped
                // values are select-discarded, never arithmetic inputs).
                const float left  = s_tile[slot * PITCH + c - 1 + (c == 0 ? 1 : 0)];
                const float right = s_tile[slot * PITCH + c + 4 - (c + 4 == NY ? 1 : 0)];

                const float d0 = (c == 0)      ? (cur.y - cur.x) * 2.0f : (cur.y - left);
                const float d1 = cur.z - cur.x;
                const float d2 = cur.w - cur.y;
                const float d3 = (c + 4 == NY) ? (cur.w - cur.z) * 2.0f : (right - cur.z);

                acc += ex * ex + d0 * d0;
                acc += ey * ey + d1 * d1;
                acc += ez * ez + d2 * d2;
                acc += ew * ew + d3 * d3;

                w0 = w1;
                w1 = down;
            }
        }
    }

    // ---- block reduction ----
    #pragma unroll
    for (int off = 16; off; off >>= 1)
        acc += __shfl_xor_sync(0xffffffffu, acc, off);

    if ((tid & 31) == 0)
        s_warp[tid >> 5] = acc;
    __syncthreads();

    if (tid < 32) {
        float v = (tid < BLOCK / 32) ? s_warp[tid] : 0.0f;
        #pragma unroll
        for (int off = 4; off; off >>= 1)
            v += __shfl_xor_sync(0xffffffffu, v, off);
        if (tid == 0) {
            g_partials[blockIdx.x] = (double)v;
            __threadfence();
            unsigned int tk = atomicAdd(&g_ticket, 1u);
            s_is_last = (tk == (unsigned int)(gridDim.x - 1));
        }
    }
    __syncthreads();

    // ---- last block: sum 128 double partials, scale, write, reset ----
    if (s_is_last) {
        double d = 0.0;
        if (tid < NUM_BLOCKS)
            d = g_partials[tid];
        #pragma unroll
        for (int off = 16; off; off >>= 1)
            d += __shfl_xor_sync(0xffffffffu, d, off);

        if ((tid & 31) == 0)
            s_dwarp[tid >> 5] = d;
        __syncthreads();
        if (tid < 32) {
            double v = (tid < BLOCK / 32) ? s_dwarp[tid] : 0.0;
            #pragma unroll
            for (int off = 4; off; off >>= 1)
                v += __shfl_xor_sync(0xffffffffu, v, off);
            if (tid == 0) {
                out[0] = (float)(v * FINAL_SCALE);
                g_ticket = 0;   // reset for next (graph-replayed) launch
            }
        }
    }
}

extern "C" void kernel_launch(void* const* d_in, const int* in_sizes, int n_in,
                              void* d_out, int out_size)
{
    // Select phi by element count (2048*2048); 'pos' (2,000,000 elems) unused.
    const float* phi = nullptr;
    for (int i = 0; i < n_in; ++i) {
        if (in_sizes[i] == NX * NY) { phi = (const float*)d_in[i]; break; }
    }
    if (!phi) phi = (const float*)d_in[n_in - 1];

    static bool attr_done = false;
    if (!attr_done) {
        cudaFuncSetAttribute(flow_energy_kernel,
                             cudaFuncAttributeMaxDynamicSharedMemorySize,
                             TILE_BYTES);
        attr_done = true;
    }

    flow_energy_kernel<<<NUM_BLOCKS, BLOCK, TILE_BYTES>>>(phi, (float*)d_out);
}